// round 2
// baseline (speedup 1.0000x reference)
#include <cuda_runtime.h>
#include <math.h>

#define BB 64
#define SS 1024
#define DK 128
#define DV 128

// Inverse key norms, precomputed (no memory-state dependence). 256 KB static scratch.
__device__ float g_invn[BB * SS];

// ---------------------------------------------------------------------------
// Pre-pass: inv_norm[b,s] = 1 / (||key[b,s,:]|| + 1e-6)
// One warp per (b,s) row; lane loads float4 (4 elems), warp shfl reduce.
// ---------------------------------------------------------------------------
__global__ void knorm_kernel(const float* __restrict__ key) {
    int row = blockIdx.x * 8 + (threadIdx.x >> 5);
    int lane = threadIdx.x & 31;
    if (row >= BB * SS) return;
    const float4* kp = reinterpret_cast<const float4*>(key + (size_t)row * DK);
    float4 kv = kp[lane];
    float ss = kv.x * kv.x + kv.y * kv.y + kv.z * kv.z + kv.w * kv.w;
    #pragma unroll
    for (int o = 16; o; o >>= 1) ss += __shfl_xor_sync(0xffffffffu, ss, o);
    if (lane == 0) g_invn[row] = 1.0f / (sqrtf(ss) + 1e-6f);
}

// ---------------------------------------------------------------------------
// Main sequential scan. One CTA per batch, 128 threads, thread t owns memory
// row t (128 fp32 in registers). Double-buffered shared k_n + reduce scratch.
// ---------------------------------------------------------------------------
__global__ __launch_bounds__(128, 1) void sgm_kernel(
    const float* __restrict__ memory,
    const float* __restrict__ key,
    const float* __restrict__ value,
    float* __restrict__ out)
{
    const int b = blockIdx.x;
    const int t = threadIdx.x;
    const int lane = t & 31;
    const int wid = t >> 5;

    __shared__ float skn[2][DK];
    __shared__ float red[2][4];

    const float* kb = key   + (size_t)b * SS * DK;
    const float* vb = value + (size_t)b * SS * DV;
    const float* ib = g_invn + (size_t)b * SS;

    // Load memory row t into registers.
    float m[DK];
    #pragma unroll
    for (int j = 0; j < DK; j += 4) {
        float4 mv = *reinterpret_cast<const float4*>(
            memory + (size_t)b * DV * DK + (size_t)t * DK + j);
        m[j] = mv.x; m[j + 1] = mv.y; m[j + 2] = mv.z; m[j + 3] = mv.w;
    }

    // Preload step 0 into buffer 0.
    skn[0][t] = kb[t] * ib[0];
    float vcur = vb[t];
    __syncthreads();

    float* gates = out + (size_t)BB * DV * DK + (size_t)b * SS;

    for (int s = 0; s < SS; ++s) {
        const int cur = s & 1;
        const int nxt = cur ^ 1;

        // Prefetch step s+1 (global loads issued early; consumed at loop end).
        float knext = 0.0f, vnext = 0.0f;
        if (s + 1 < SS) {
            knext = kb[(size_t)(s + 1) * DK + t] * ib[s + 1];
            vnext = vb[(size_t)(s + 1) * DV + t];
        }

        // predicted[t] = dot(m_row_t, k_n)  (shared reads are warp-broadcast)
        const float4* knv = reinterpret_cast<const float4*>(skn[cur]);
        float a0 = 0.f, a1 = 0.f, a2 = 0.f, a3 = 0.f;
        #pragma unroll
        for (int jj = 0; jj < DK / 4; ++jj) {
            float4 kv = knv[jj];
            a0 += m[4 * jj + 0] * kv.x;
            a1 += m[4 * jj + 1] * kv.y;
            a2 += m[4 * jj + 2] * kv.z;
            a3 += m[4 * jj + 3] * kv.w;
        }
        float pred = (a0 + a1) + (a2 + a3);
        float sur = pred - vcur;

        // s_norm^2 = block-sum of surprise^2 over the 128 DV rows.
        float ss2 = sur * sur;
        #pragma unroll
        for (int o = 16; o; o >>= 1) ss2 += __shfl_xor_sync(0xffffffffu, ss2, o);
        if (lane == 0) red[cur][wid] = ss2;
        __syncthreads();
        float tot = red[cur][0] + red[cur][1] + red[cur][2] + red[cur][3];
        float snorm = sqrtf(tot);
        // gate = sigmoid((snorm - 0.1)/0.1); saturates to 1.0 for typical snorm
        float gate = 1.0f / (1.0f + __expf((0.1f - snorm) * 10.0f));
        float coef = gate * (pred + 0.1f * sur);

        // mem_row_t -= coef * k_n
        #pragma unroll
        for (int jj = 0; jj < DK / 4; ++jj) {
            float4 kv = knv[jj];
            m[4 * jj + 0] -= coef * kv.x;
            m[4 * jj + 1] -= coef * kv.y;
            m[4 * jj + 2] -= coef * kv.z;
            m[4 * jj + 3] -= coef * kv.w;
        }

        if (t == 0) gates[s] = gate;

        // Stage next step's k_n into the other buffer; safe: nobody reads it yet.
        skn[nxt][t] = knext;
        vcur = vnext;
        __syncthreads();
    }

    // Store final memory.
    #pragma unroll
    for (int j = 0; j < DK; j += 4) {
        float4 mv = make_float4(m[j], m[j + 1], m[j + 2], m[j + 3]);
        *reinterpret_cast<float4*>(
            out + (size_t)b * DV * DK + (size_t)t * DK + j) = mv;
    }
}

extern "C" void kernel_launch(void* const* d_in, const int* in_sizes, int n_in,
                              void* d_out, int out_size) {
    const float* memory = (const float*)d_in[0];
    const float* key    = (const float*)d_in[1];
    const float* value  = (const float*)d_in[2];
    float* out = (float*)d_out;

    knorm_kernel<<<(BB * SS) / 8, 256>>>(key);
    sgm_kernel<<<BB, 128>>>(memory, key, value, out);
}